// round 16
// baseline (speedup 1.0000x reference)
#include <cuda_runtime.h>
#include <math.h>

typedef unsigned long long ull;

#define BB 64
#define TT 512
#define II 256
#define HH 512
#define CC 40
#define G4 2048     // 4*H
#define NB 128      // persistent blocks, all co-resident (<=148 SMs, 1 block/SM)
#define NT_LSTM 576 // 2 gate warps + 16 compute warps

// -------------------- device scratch --------------------
__device__ __align__(256) float g_xg [(size_t)BB * TT * G4];   // [m=b*T+t][n]
__device__ __align__(256) float g_xgT[(size_t)TT * G4 * BB];   // [t][n][b]
__device__ __align__(256) float g_hbuf[2 * HH * BB];           // [parity][unit][b]
__device__ volatile unsigned g_stepflag[NB * 32];              // one 128B line per block (padded — proven)

// -------------------- f32x2 helpers --------------------
__device__ __forceinline__ ull pack2(float x, float y) {
    ull r; asm("mov.b64 %0, {%1, %2};" : "=l"(r) : "f"(x), "f"(y)); return r;
}
__device__ __forceinline__ void unpack2(ull v, float& x, float& y) {
    asm("mov.b64 {%0, %1}, %2;" : "=f"(x), "=f"(y) : "l"(v));
}
__device__ __forceinline__ ull ffma2(ull a, ull b, ull c) {
    ull d; asm("fma.rn.f32x2 %0, %1, %2, %3;" : "=l"(d) : "l"(a), "l"(b), "l"(c)); return d;
}
// 32B L2 (.cg) load as four ulls
__device__ __forceinline__ void ldcg32(const void* p, ull& a, ull& b, ull& c, ull& d) {
    asm volatile("ld.global.cg.v2.u64 {%0, %1}, [%2];" : "=l"(a), "=l"(b) : "l"(p));
    asm volatile("ld.global.cg.v2.u64 {%0, %1}, [%2];" : "=l"(c), "=l"(d) : "l"((const char*)p + 16));
}

// fast activations (MUFU-based; err ~1e-6, well within 1e-3 budget)
__device__ __forceinline__ float fsig(float x) {
    return __fdividef(1.f, 1.f + __expf(-x));
}
__device__ __forceinline__ float ftanh(float x) {
    float ax = fabsf(x);
    float e  = __expf(-2.f * ax);
    float r  = __fdividef(1.f - e, 1.f + e);
    return x < 0.f ? -r : r;
}

// -------------------- kernel 1: xg = x @ W_ih^T + (b_ih + b_hh), f32x2 --------------------
__global__ void __launch_bounds__(256) gemm_xg(const float* __restrict__ x,
                                               const float* __restrict__ Wih,
                                               const float* __restrict__ bih,
                                               const float* __restrict__ bhh) {
    __shared__ __align__(16) float As[16][132];   // [k][m]
    __shared__ __align__(16) float Bs[16][132];   // [k][n] permuted
    const int tid  = threadIdx.x;
    const int m0   = blockIdx.y * 128;
    const int n0   = blockIdx.x * 128;
    const int tx   = tid & 15;
    const int ty   = tid >> 4;
    const int lrow = tid >> 2;
    const int lkq  = (tid & 3) << 2;
    char* BsB = (char*)Bs;

    ull acc2[8][4];
#pragma unroll
    for (int i = 0; i < 8; i++)
#pragma unroll
        for (int j = 0; j < 4; j++) acc2[i][j] = 0ull;

    const unsigned posA = ((unsigned)(tx & 1)) * 256u + ((unsigned)(tx >> 1)) * 16u;

    for (int k0 = 0; k0 < II; k0 += 16) {
        float4 a0 = *(const float4*)(x   + (size_t)(m0 + lrow)      * II + k0 + lkq);
        float4 a1 = *(const float4*)(x   + (size_t)(m0 + lrow + 64) * II + k0 + lkq);
        float4 b0 = *(const float4*)(Wih + (size_t)(n0 + lrow)      * II + k0 + lkq);
        float4 b1 = *(const float4*)(Wih + (size_t)(n0 + lrow + 64) * II + k0 + lkq);
        __syncthreads();
        As[lkq+0][lrow]    = a0.x; As[lkq+1][lrow]    = a0.y;
        As[lkq+2][lrow]    = a0.z; As[lkq+3][lrow]    = a0.w;
        As[lkq+0][lrow+64] = a1.x; As[lkq+1][lrow+64] = a1.y;
        As[lkq+2][lrow+64] = a1.z; As[lkq+3][lrow+64] = a1.w;
        {
            int c0 = lrow, c1 = lrow + 64;
            unsigned o0 = (unsigned)(((c0 >> 2) & 3) << 7) + (unsigned)((c0 >> 4) << 4) + (unsigned)((c0 & 3) << 2);
            unsigned o1 = (unsigned)(((c1 >> 2) & 3) << 7) + (unsigned)((c1 >> 4) << 4) + (unsigned)((c1 & 3) << 2);
            *(float*)(BsB + (lkq+0)*528 + o0) = b0.x;
            *(float*)(BsB + (lkq+1)*528 + o0) = b0.y;
            *(float*)(BsB + (lkq+2)*528 + o0) = b0.z;
            *(float*)(BsB + (lkq+3)*528 + o0) = b0.w;
            *(float*)(BsB + (lkq+0)*528 + o1) = b1.x;
            *(float*)(BsB + (lkq+1)*528 + o1) = b1.y;
            *(float*)(BsB + (lkq+2)*528 + o1) = b1.z;
            *(float*)(BsB + (lkq+3)*528 + o1) = b1.w;
        }
        __syncthreads();
#pragma unroll
        for (int k = 0; k < 16; k++) {
            float a[8];
            *(float4*)(a)     = *(float4*)&As[k][ty * 8];
            *(float4*)(a + 4) = *(float4*)&As[k][ty * 8 + 4];
            ulonglong2 bA = *(ulonglong2*)(BsB + k*528 + posA);
            ulonglong2 bB = *(ulonglong2*)(BsB + k*528 + posA + 128);
            ull b2[4] = {bA.x, bA.y, bB.x, bB.y};
#pragma unroll
            for (int i = 0; i < 8; i++) {
                ull a2 = pack2(a[i], a[i]);
                acc2[i][0] = ffma2(a2, b2[0], acc2[i][0]);
                acc2[i][1] = ffma2(a2, b2[1], acc2[i][1]);
                acc2[i][2] = ffma2(a2, b2[2], acc2[i][2]);
                acc2[i][3] = ffma2(a2, b2[3], acc2[i][3]);
            }
        }
    }

    float bias[8];
#pragma unroll
    for (int j = 0; j < 8; j++) {
        int n = n0 + tx * 8 + j;
        bias[j] = bih[n] + bhh[n];
    }
#pragma unroll
    for (int i = 0; i < 8; i++) {
        size_t m = (size_t)(m0 + ty * 8 + i);
        float o[8];
#pragma unroll
        for (int j = 0; j < 4; j++) unpack2(acc2[i][j], o[2*j], o[2*j+1]);
        float4 v0, v1;
        v0.x = o[0] + bias[0]; v0.y = o[1] + bias[1];
        v0.z = o[2] + bias[2]; v0.w = o[3] + bias[3];
        v1.x = o[4] + bias[4]; v1.y = o[5] + bias[5];
        v1.z = o[6] + bias[6]; v1.w = o[7] + bias[7];
        *(float4*)(g_xg + m * G4 + n0 + tx * 8)     = v0;
        *(float4*)(g_xg + m * G4 + n0 + tx * 8 + 4) = v1;
    }
}

// -------------------- kernel 2: transpose xg[b*T+t][n] -> xgT[t][n][b] --------------------
__global__ void __launch_bounds__(256) transpose_xg() {
    __shared__ float tile[64][65];
    const int t   = blockIdx.x;
    const int n0  = blockIdx.y << 6;
    const int tid = threadIdx.x;
    const int a   = tid & 63;
    const int r   = tid >> 6;
    for (int b = r; b < 64; b += 4)
        tile[a][b] = g_xg[(size_t)(b * TT + t) * G4 + n0 + a];
    __syncthreads();
    for (int n = r; n < 64; n += 4)
        g_xgT[((size_t)t * G4 + n0 + n) * BB + a] = tile[n][a];
}

// -------------------- noop: capture-window alignment for ncu --------------------
__global__ void noop_pad() {}

// -------------------- kernel 3: persistent LSTM recurrence --------------------
// Warp-specialized (576 threads = 2 gate warps + 16 compute warps), batch-split
// tiling (8 units x 32 batches per block), padded-flag dataflow sync (proven):
//  * Compute warps (wid 2..17, kg=wid-2): poll 4 producers' padded flags in one
//    instr -> FMA k-split [32kg,32kg+32) from L2 -> store red[t&1] -> syncthreads
//    -> straight to step t+1 (red double-buffered; they never idle in elementwise).
//  * Gate warps (tid<64, 4 cells/thread): syncthreads -> float4 LDS.128 reduce
//    (contiguous 512B per (k2,g): conflict-free) + xg (prefetched float4) ->
//    activations -> c/h update (c[4] regs, float4 h store) -> bar.sync 7,64 ->
//    tid0 fence + flag publish (no full-block second sync).
// smem: Wsm float [512][32] 64KB | red[2][16][32][32] 128KB = 192KB
#define SMEM_LSTM (65536 + 131072)
__global__ void __launch_bounds__(NT_LSTM, 1) lstm_rec(const float* __restrict__ Whh) {
    extern __shared__ char smc[];
    float* Wsm  = (float*)smc;               // [512][32]  w[k][lr]
    float* red  = (float*)(smc + 65536);     // [2][16][32][32]
    ull*   red2 = (ull*)red;

    const int tid  = threadIdx.x;
    const int bx   = blockIdx.x;
    const int ublk = bx >> 1;                // unit group (8 units)
    const int bh   = bx & 1;                 // batch half
    const unsigned S = g_stepflag[bx * 32];  // epoch base (persistent across replays)

    // Load W_hh slice: Wsm[k*32 + lr] = Whh[row(lr)][k], lr = g*8+u
    for (int idx = tid; idx < 32 * 512; idx += NT_LSTM) {
        int k   = idx >> 5;
        int lr  = idx & 31;
        int row = ((lr >> 3) << 9) + (ublk << 3) + (lr & 7);
        Wsm[(k << 5) + lr] = Whh[(size_t)row * HH + k];
    }

    // ---- gate-role constants (tid < 64): 4 cells = (unit uu, batches 4*bq4..+3)
    const int uu  = tid >> 3;        // 0..7
    const int bq4 = tid & 7;         // 0..7
    const int ug  = (ublk << 3) + uu;
    const int hoff = ug * 64 + (bh << 5) + (bq4 << 2);   // float idx of this thread's 4 h cells

    if (tid < 64) *(float4*)(g_hbuf + hoff) = make_float4(0.f, 0.f, 0.f, 0.f);  // h0 (parity 0)
    float c0v = 0.f, c1v = 0.f, c2v = 0.f, c3v = 0.f;
    __syncthreads();
    if (tid == 0) { __threadfence(); g_stepflag[bx * 32] = S + 1; }  // h_0 ready

    if (tid < 64) {
        // ================= gate warps =================
        float4 xgv[4];
#pragma unroll
        for (int g = 0; g < 4; g++)
            xgv[g] = *(const float4*)(g_xgT + ((size_t)0 * G4 + (g << 9) + ug) * 64 + (bh << 5) + (bq4 << 2));

        for (int t = 0; t < TT; t++) {
            const int p = t & 1;
            __syncthreads();    // red[p] complete (all 16 compute warps stored)

            // reduce 16 split-k partials (float4) + xg
            float4 s4[4];
#pragma unroll
            for (int g = 0; g < 4; g++) {
                const int lr = (g << 3) + uu;
                const float* rp = red + (p << 14) + (lr << 5) + (bq4 << 2);
                float4 a = *(const float4*)(rp);
#pragma unroll
                for (int k2 = 1; k2 < 16; k2++) {
                    float4 r = *(const float4*)(rp + (k2 << 10));
                    a.x += r.x; a.y += r.y; a.z += r.z; a.w += r.w;
                }
                s4[g].x = a.x + xgv[g].x; s4[g].y = a.y + xgv[g].y;
                s4[g].z = a.z + xgv[g].z; s4[g].w = a.w + xgv[g].w;
            }

            // activations + state update for 4 cells
            float4 hv;
            {
                float ig, fg, gg, og;
                ig = fsig(s4[0].x); fg = fsig(s4[1].x); gg = ftanh(s4[2].x); og = fsig(s4[3].x);
                c0v = fmaf(fg, c0v, ig * gg); hv.x = og * ftanh(c0v);
                ig = fsig(s4[0].y); fg = fsig(s4[1].y); gg = ftanh(s4[2].y); og = fsig(s4[3].y);
                c1v = fmaf(fg, c1v, ig * gg); hv.y = og * ftanh(c1v);
                ig = fsig(s4[0].z); fg = fsig(s4[1].z); gg = ftanh(s4[2].z); og = fsig(s4[3].z);
                c2v = fmaf(fg, c2v, ig * gg); hv.z = og * ftanh(c2v);
                ig = fsig(s4[0].w); fg = fsig(s4[1].w); gg = ftanh(s4[2].w); og = fsig(s4[3].w);
                c3v = fmaf(fg, c3v, ig * gg); hv.w = og * ftanh(c3v);
            }
            *(float4*)(g_hbuf + ((p ^ 1) * HH * 64) + hoff) = hv;   // h_{t+1}

            asm volatile("bar.sync 7, 64;" ::: "memory");          // gate warps only
            if (tid == 0) { __threadfence(); g_stepflag[bx * 32] = S + 2 + (unsigned)t; }

            // prefetch xg for next step
            if (t + 1 < TT) {
#pragma unroll
                for (int g = 0; g < 4; g++)
                    xgv[g] = *(const float4*)(g_xgT + ((size_t)(t + 1) * G4 + (g << 9) + ug) * 64 + (bh << 5) + (bq4 << 2));
            }
        }
    } else {
        // ================= compute warps =================
        const int kg   = (tid >> 5) - 2;   // 0..15 = k-split, krange 32
        const int lane = tid & 31;
        const int rq   = lane >> 2;        // rows 4rq..4rq+3 (of 32 local rows)
        const int bq   = lane & 3;         // batches 8bq..8bq+7 (of 32)
        const int prod = ((((kg << 2) + (lane & 3)) << 1) + bh) * 32;  // producer flags (padded)
        const float* wk0 = Wsm + (kg << 10) + (rq << 2);
        const int rbase = (kg << 9) + (rq << 6) + (bq << 2);           // red2 ull base within buffer
        const int krow0 = kg << 5;

        for (int t = 0; t < TT; t++) {
            const int p = t & 1;

            // wait for this warp's 4 producers (parallel poll, one instr per retry)
            {
                const unsigned want = S + 1 + (unsigned)t;
                while ((int)(g_stepflag[prod] - want) < 0) { }
                __syncwarp();
                __threadfence();   // acquire: order h reads after flag observation
            }

            ull acc[4][4];
#pragma unroll
            for (int j = 0; j < 4; j++)
#pragma unroll
                for (int u = 0; u < 4; u++) acc[j][u] = 0ull;

            const char* hk = (const char*)(g_hbuf + (size_t)p * HH * 64)
                           + (krow0 << 8) + (bh << 7) + (bq << 5);   // k*256B + half*128B + bq*32B
            const float* wk = wk0;
#pragma unroll 4
            for (int k = 0; k < 32; k++) {
                ull hx, hy, hz, hw;
                ldcg32(hk, hx, hy, hz, hw);                  // 8 batches of h[k] (this half)
                float4 wv = *(const float4*)wk;              // rows 4rq..4rq+3 at this k
                hk += 256; wk += 32;
                ull w0 = pack2(wv.x, wv.x);
                ull w1 = pack2(wv.y, wv.y);
                ull w2 = pack2(wv.z, wv.z);
                ull w3 = pack2(wv.w, wv.w);
                acc[0][0] = ffma2(w0, hx, acc[0][0]);
                acc[0][1] = ffma2(w0, hy, acc[0][1]);
                acc[0][2] = ffma2(w0, hz, acc[0][2]);
                acc[0][3] = ffma2(w0, hw, acc[0][3]);
                acc[1][0] = ffma2(w1, hx, acc[1][0]);
                acc[1][1] = ffma2(w1, hy, acc[1][1]);
                acc[1][2] = ffma2(w1, hz, acc[1][2]);
                acc[1][3] = ffma2(w1, hw, acc[1][3]);
                acc[2][0] = ffma2(w2, hx, acc[2][0]);
                acc[2][1] = ffma2(w2, hy, acc[2][1]);
                acc[2][2] = ffma2(w2, hz, acc[2][2]);
                acc[2][3] = ffma2(w2, hw, acc[2][3]);
                acc[3][0] = ffma2(w3, hx, acc[3][0]);
                acc[3][1] = ffma2(w3, hy, acc[3][1]);
                acc[3][2] = ffma2(w3, hz, acc[3][2]);
                acc[3][3] = ffma2(w3, hw, acc[3][3]);
            }

            ull* rb = red2 + (p << 13) + rbase;   // double-buffered red
#pragma unroll
            for (int j = 0; j < 4; j++) {
                *(ulonglong2*)(rb + j * 16)     = make_ulonglong2(acc[j][0], acc[j][1]);
                *(ulonglong2*)(rb + j * 16 + 2) = make_ulonglong2(acc[j][2], acc[j][3]);
            }
            __syncthreads();    // hand red[p] to gate warps; then run ahead
        }
    }
    // h_last = h_512 in parity 0
}

// -------------------- kernel 4: out = h_last @ W_fc^T + b_fc --------------------
__global__ void __launch_bounds__(256) fc_out(const float* __restrict__ Wfc,
                                              const float* __restrict__ bfc,
                                              float* __restrict__ out) {
    __shared__ float hs[HH];
    const int b = blockIdx.x;
    for (int u = threadIdx.x; u < HH; u += 256) hs[u] = g_hbuf[u * 64 + b];
    __syncthreads();
    const int w = threadIdx.x >> 5, lane = threadIdx.x & 31;
    for (int cc = w; cc < CC; cc += 8) {
        float s = 0.f;
        for (int u = lane; u < HH; u += 32) s = fmaf(hs[u], Wfc[cc * HH + u], s);
#pragma unroll
        for (int o = 16; o; o >>= 1) s += __shfl_xor_sync(0xffffffffu, s, o);
        if (lane == 0) out[b * CC + cc] = s + bfc[cc];
    }
}

// -------------------- launch --------------------
extern "C" void kernel_launch(void* const* d_in, const int* in_sizes, int n_in,
                              void* d_out, int out_size) {
    (void)in_sizes; (void)n_in; (void)out_size;
    const float* x   = (const float*)d_in[0];
    const float* Wih = (const float*)d_in[1];
    const float* Whh = (const float*)d_in[2];
    const float* bih = (const float*)d_in[3];
    const float* bhh = (const float*)d_in[4];
    const float* Wfc = (const float*)d_in[5];
    const float* bfc = (const float*)d_in[6];
    float* out = (float*)d_out;

    gemm_xg<<<dim3(G4 / 128, (BB * TT) / 128), 256>>>(x, Wih, bih, bhh);
    transpose_xg<<<dim3(TT, G4 / 64), 256>>>();
    noop_pad<<<1, 32>>>();   // aligns ncu capture index onto lstm_rec

    cudaFuncSetAttribute(lstm_rec, cudaFuncAttributeMaxDynamicSharedMemorySize, SMEM_LSTM);
    lstm_rec<<<NB, NT_LSTM, SMEM_LSTM>>>(Whh);

    fc_out<<<BB, 256>>>(Wfc, bfc, out);
}